// round 9
// baseline (speedup 1.0000x reference)
#include <cuda_runtime.h>
#include <cstdint>

#define LW 49
#define DK 32
#define NH 8
#define NW 64
#define LP 52      // padded k row length (13 float4)
#define RST 50     // bias+mask row stride (8B-aligned pairs)
#define BMSZ 2452  // 49*50 padded to float4 multiple

// Fused (bias + mask) for each of the 512 (h,w) combos, rows padded to RST.
__device__ float g_bm[NH * NW * BMSZ];

__global__ void bm_prep_kernel(const float* __restrict__ table,
                               const int* __restrict__ idx,
                               const float* __restrict__ mask) {
    const int hw = blockIdx.x;          // h*NW + w
    const int h  = hw >> 6;
    const int w  = hw & (NW - 1);
    float* __restrict__ dst = g_bm + (size_t)hw * BMSZ;
    const float* __restrict__ mg = mask + (size_t)w * (LW * LW);
    for (int i = threadIdx.x; i < BMSZ; i += blockDim.x) {
        int t = i / RST, s = i - t * RST;
        float v = 0.f;
        if (t < LW && s < LW) v = table[idx[t * LW + s] * NH + h] + mg[t * LW + s];
        dst[i] = v;
    }
}

// ---- packed fp32 helpers (Blackwell f32x2 path) ----
__device__ __forceinline__ unsigned long long fma2(unsigned long long a,
                                                   unsigned long long b,
                                                   unsigned long long c) {
    unsigned long long d;
    asm("fma.rn.f32x2 %0, %1, %2, %3;" : "=l"(d) : "l"(a), "l"(b), "l"(c));
    return d;
}
__device__ __forceinline__ unsigned long long mul2(unsigned long long a,
                                                   unsigned long long b) {
    unsigned long long d;
    asm("mul.rn.f32x2 %0, %1, %2;" : "=l"(d) : "l"(a), "l"(b));
    return d;
}
__device__ __forceinline__ unsigned long long pack2(float x, float y) {
    unsigned long long d;
    asm("mov.b64 %0, {%1, %2};" : "=l"(d) : "f"(x), "f"(y));
    return d;
}
__device__ __forceinline__ void unpack2(unsigned long long p, float& x, float& y) {
    asm("mov.b64 {%0, %1}, %2;" : "=f"(x), "=f"(y) : "l"(p));
}
__device__ __forceinline__ void lds_v2u64(uint32_t a, unsigned long long& x,
                                          unsigned long long& y) {
    asm volatile("ld.shared.v2.u64 {%0, %1}, [%2];" : "=l"(x), "=l"(y) : "r"(a));
}
__device__ __forceinline__ unsigned long long lds_u64(uint32_t a) {
    unsigned long long v;
    asm volatile("ld.shared.u64 %0, [%1];" : "=l"(v) : "r"(a));
    return v;
}
__device__ __forceinline__ void sts_u64(uint32_t a, unsigned long long v) {
    asm volatile("st.shared.u64 [%0], %1;" :: "r"(a), "l"(v));
}
__device__ __forceinline__ float lds_f32(uint32_t a) {
    float v;
    asm volatile("ld.shared.f32 %0, [%1];" : "=f"(v) : "r"(a));
    return v;
}

// One CTA = two (b,h) pairs, one per warp. Warp lane i computes rows i and i+32.
__global__ __launch_bounds__(64)
void win_attn_kernel(const float* __restrict__ q,
                     const float* __restrict__ k,
                     float* __restrict__ out_score,
                     float* __restrict__ out_attn) {
    __shared__ __align__(16) float qs[2][DK * LP];
    __shared__ __align__(16) float ks[2][DK * LP];
    __shared__ __align__(16) float bm[2][BMSZ];

    const int tid  = threadIdx.x;
    const int wid  = tid >> 5;
    const int lane = tid & 31;
    const int bh   = blockIdx.x * 2 + wid;
    const int h    = bh & 7;
    const int w    = (bh >> 3) & (NW - 1);

    const float* __restrict__ qg = q + (size_t)bh * (DK * LW);
    const float* __restrict__ kg = k + (size_t)bh * (DK * LW);

    // ---- stage q,k (pad tail zeroed), and fused bias+mask ----
    for (int i = lane; i < 96; i += 32) {
        int c = i / 3, r = i - c * 3;
        qs[wid][c * LP + 49 + r] = 0.f;
        ks[wid][c * LP + 49 + r] = 0.f;
    }
    for (int j = lane; j < 392; j += 32) {
        float4 qv = ((const float4*)qg)[j];
        float4 kv = ((const float4*)kg)[j];
        float qa[4] = {qv.x, qv.y, qv.z, qv.w};
        float ka[4] = {kv.x, kv.y, kv.z, kv.w};
        int e = j * 4;
        #pragma unroll
        for (int u = 0; u < 4; u++) {
            int ee = e + u;
            int c  = ee / LW;
            int t  = ee - c * LW;
            qs[wid][c * LP + t] = qa[u];
            ks[wid][c * LP + t] = ka[u];
        }
    }
    {
        const float* __restrict__ bmg = g_bm + (size_t)(h * NW + w) * BMSZ;
        for (int i = lane; i < BMSZ / 4; i += 32)
            ((float4*)bm[wid])[i] = ((const float4*)bmg)[i];
    }
    __syncwarp();

    const uint32_t ksb = (uint32_t)__cvta_generic_to_shared(&ks[wid][0]);
    const uint32_t qsb = (uint32_t)__cvta_generic_to_shared(&qs[wid][0]);
    const uint32_t bmb = (uint32_t)__cvta_generic_to_shared(&bm[wid][0]);

    const int  r0 = lane;
    const bool v1 = (lane < 17);
    const int  r1 = v1 ? lane + 32 : 48;   // clamped; results discarded when !v1

    // ---- phase 1: packed logits, 2 rows per thread, shared k stream ----
    unsigned long long acc0[26], acc1[26];
    #pragma unroll
    for (int p = 0; p < 26; p++) { acc0[p] = 0ull; acc1[p] = 0ull; }

    #pragma unroll 2
    for (int c = 0; c < DK; c++) {
        const uint32_t rowb = ksb + (uint32_t)(c * LP) * 4u;
        float q0 = lds_f32(qsb + (uint32_t)(c * LP + r0) * 4u);
        float q1 = lds_f32(qsb + (uint32_t)(c * LP + r1) * 4u);
        unsigned long long q0p = pack2(q0, q0);
        unsigned long long q1p = pack2(q1, q1);
        #pragma unroll
        for (int j = 0; j < 13; j++) {
            unsigned long long k0, k1;
            lds_v2u64(rowb + j * 16, k0, k1);
            acc0[2 * j]     = fma2(q0p, k0, acc0[2 * j]);
            acc0[2 * j + 1] = fma2(q0p, k1, acc0[2 * j + 1]);
            acc1[2 * j]     = fma2(q1p, k0, acc1[2 * j]);
            acc1[2 * j + 1] = fma2(q1p, k1, acc1[2 * j + 1]);
        }
    }

    // ---- softmax (packed where possible) ----
    const float scale = 0.17677669529663687f;  // 32^-0.5
    const unsigned long long scale2 = pack2(scale, scale);
    const uint32_t bmr0 = bmb + (uint32_t)(r0 * RST) * 4u;
    const uint32_t bmr1 = bmb + (uint32_t)(r1 * RST) * 4u;

    #define SOFTMAX_ROW(ACC, BMR)                                            \
    {                                                                        \
        float mx = -1e30f, u, v;                                             \
        _Pragma("unroll")                                                    \
        for (int p = 0; p < 24; p++) {                                       \
            ACC[p] = fma2(ACC[p], scale2, lds_u64(BMR + p * 8));             \
            unpack2(ACC[p], u, v);                                           \
            mx = fmaxf(mx, fmaxf(u, v));                                     \
        }                                                                    \
        unpack2(ACC[24], u, v);                                              \
        float x48 = fmaf(u, scale, lds_f32(BMR + 48 * 4));                   \
        mx = fmaxf(mx, x48);                                                 \
        float sum = 0.f;                                                     \
        _Pragma("unroll")                                                    \
        for (int p = 0; p < 24; p++) {                                       \
            unpack2(ACC[p], u, v);                                           \
            u = __expf(u - mx); v = __expf(v - mx);                          \
            sum += u + v;                                                    \
            ACC[p] = pack2(u, v);                                            \
        }                                                                    \
        float e48 = __expf(x48 - mx);                                        \
        sum += e48;                                                          \
        ACC[24] = pack2(e48, 0.f);                                           \
        float inv = 1.0f / sum;                                              \
        unsigned long long inv2 = pack2(inv, inv);                           \
        _Pragma("unroll")                                                    \
        for (int p = 0; p < 25; p++) ACC[p] = mul2(ACC[p], inv2);            \
        ACC[25] = 0ull;                                                      \
    }

    SOFTMAX_ROW(acc0, bmr0)
    SOFTMAX_ROW(acc1, bmr1)

    // write probability rows back into bm (packed, own rows only)
    #pragma unroll
    for (int p = 0; p < 25; p++) sts_u64(bmr0 + p * 8, acc0[p]);
    if (v1) {
        #pragma unroll
        for (int p = 0; p < 25; p++) sts_u64(bmr1 + p * 8, acc1[p]);
    }

    // ---- phase 2: score[c][t] = sum_s p[s] * k[c][s] (V := K), shared k stream ----
    float* __restrict__ og = out_score + (size_t)bh * (DK * LW);
    #pragma unroll 2
    for (int c = 0; c < DK; c++) {
        const uint32_t rowb = ksb + (uint32_t)(c * LP) * 4u;
        unsigned long long s0 = 0ull, s1 = 0ull;
        #pragma unroll
        for (int j = 0; j < 13; j++) {
            unsigned long long k0, k1;
            lds_v2u64(rowb + j * 16, k0, k1);
            s0 = fma2(acc0[2 * j], k0, s0);
            s0 = fma2(acc0[2 * j + 1], k1, s0);
            s1 = fma2(acc1[2 * j], k0, s1);
            s1 = fma2(acc1[2 * j + 1], k1, s1);
        }
        float a, b, x, y;
        unpack2(s0, a, b);
        unpack2(s1, x, y);
        og[c * LW + r0] = a + b;
        if (v1) og[c * LW + r1] = x + y;
    }
    __syncwarp();

    // ---- coalesced attn write-out from SMEM (rows are RST-padded) ----
    float* __restrict__ ag = out_attn + (size_t)bh * (LW * LW);
    for (int i = lane; i < LW * LW; i += 32) {
        int t = i / LW, s = i - t * LW;
        ag[i] = bm[wid][t * RST + s];
    }
}

extern "C" void kernel_launch(void* const* d_in, const int* in_sizes, int n_in,
                              void* d_out, int out_size) {
    const float* q     = (const float*)d_in[0];
    const float* k     = (const float*)d_in[1];
    // d_in[2] (v) unused: reference sets v := k
    const float* mask  = (const float*)d_in[3];
    const float* table = (const float*)d_in[4];
    const int*   idx   = (const int*)d_in[5];

    float* out       = (float*)d_out;
    float* out_score = out;                            // 2048*256*49
    float* out_attn  = out + (size_t)2048 * 256 * 49;  // 2048*8*49*49

    bm_prep_kernel<<<NH * NW, 256>>>(table, idx, mask);
    win_attn_kernel<<<2048 * NH / 2, 64>>>(q, k, out_score, out_attn);
}

// round 12
// speedup vs baseline: 1.2753x; 1.2753x over previous
#include <cuda_runtime.h>
#include <cstdint>

#define LW 49
#define DK 32
#define NH 8
#define NW 64
#define LP 52      // padded k row length (13 float4)
#define RST 50     // bias+mask row stride (8B-aligned pairs)
#define BMSZ 2452  // 49*50 padded to float4 multiple

// Fused (bias + mask) for each of the 512 (h,w) combos, rows padded to RST.
__device__ float g_bm[NH * NW * BMSZ];

__global__ void bm_prep_kernel(const float* __restrict__ table,
                               const int* __restrict__ idx,
                               const float* __restrict__ mask) {
    const int hw = blockIdx.x;          // h*NW + w
    const int h  = hw >> 6;
    const int w  = hw & (NW - 1);
    float* __restrict__ dst = g_bm + (size_t)hw * BMSZ;
    const float* __restrict__ mg = mask + (size_t)w * (LW * LW);
    for (int i = threadIdx.x; i < BMSZ; i += blockDim.x) {
        int t = i / RST, s = i - t * RST;
        float v = 0.f;
        if (t < LW && s < LW) v = table[idx[t * LW + s] * NH + h] + mg[t * LW + s];
        dst[i] = v;
    }
}

// ---- packed fp32 helpers (Blackwell f32x2 path) ----
__device__ __forceinline__ unsigned long long fma2(unsigned long long a,
                                                   unsigned long long b,
                                                   unsigned long long c) {
    unsigned long long d;
    asm("fma.rn.f32x2 %0, %1, %2, %3;" : "=l"(d) : "l"(a), "l"(b), "l"(c));
    return d;
}
__device__ __forceinline__ unsigned long long mul2(unsigned long long a,
                                                   unsigned long long b) {
    unsigned long long d;
    asm("mul.rn.f32x2 %0, %1, %2;" : "=l"(d) : "l"(a), "l"(b));
    return d;
}
__device__ __forceinline__ unsigned long long pack2(float x, float y) {
    unsigned long long d;
    asm("mov.b64 %0, {%1, %2};" : "=l"(d) : "f"(x), "f"(y));
    return d;
}
__device__ __forceinline__ void unpack2(unsigned long long p, float& x, float& y) {
    asm("mov.b64 {%0, %1}, %2;" : "=f"(x), "=f"(y) : "l"(p));
}
__device__ __forceinline__ void lds_v2u64(uint32_t a, unsigned long long& x,
                                          unsigned long long& y) {
    asm volatile("ld.shared.v2.u64 {%0, %1}, [%2];" : "=l"(x), "=l"(y) : "r"(a));
}
__device__ __forceinline__ unsigned long long lds_u64(uint32_t a) {
    unsigned long long v;
    asm volatile("ld.shared.u64 %0, [%1];" : "=l"(v) : "r"(a));
    return v;
}
__device__ __forceinline__ void sts_u64(uint32_t a, unsigned long long v) {
    asm volatile("st.shared.u64 [%0], %1;" :: "r"(a), "l"(v));
}
__device__ __forceinline__ float lds_f32(uint32_t a) {
    float v;
    asm volatile("ld.shared.f32 %0, [%1];" : "=f"(v) : "r"(a));
    return v;
}

// CTA = 4 warps = 4 (b,h) pairs sharing one (h,w) bias+mask tile.
// Warp lane i computes attention rows i and i+32.
__global__ __launch_bounds__(128)
void win_attn_kernel(const float* __restrict__ q,
                     const float* __restrict__ k,
                     float* __restrict__ out_score,
                     float* __restrict__ out_attn) {
    __shared__ __align__(16) float ks[4][DK * LP];
    __shared__ __align__(16) float bm[BMSZ];

    const int tid  = threadIdx.x;
    const int wid  = tid >> 5;
    const int lane = tid & 31;

    const int cta = blockIdx.x;           // 64*8*8 = 4096 CTAs
    const int w   = cta & 63;
    const int h   = (cta >> 6) & 7;
    const int grp = cta >> 9;             // 0..7
    const int b   = w + 64 * (grp * 4 + wid);
    const int bh  = b * 8 + h;

    const float* __restrict__ qg = q + (size_t)bh * (DK * LW);
    const float* __restrict__ kg = k + (size_t)bh * (DK * LW);

    // ---- stage k (per warp) and shared bias+mask (whole CTA) ----
    for (int i = lane; i < 96; i += 32) {
        int c = i / 3, r = i - c * 3;
        ks[wid][c * LP + 49 + r] = 0.f;
    }
    for (int j = lane; j < 392; j += 32) {
        float4 kv = ((const float4*)kg)[j];
        float ka[4] = {kv.x, kv.y, kv.z, kv.w};
        int e = j * 4;
        #pragma unroll
        for (int u = 0; u < 4; u++) {
            int ee = e + u;
            int c  = ee / LW;
            int t  = ee - c * LW;
            ks[wid][c * LP + t] = ka[u];
        }
    }
    {
        const float* __restrict__ bmg = g_bm + (size_t)(h * NW + w) * BMSZ;
        for (int i = tid; i < BMSZ / 4; i += 128)
            ((float4*)bm)[i] = ((const float4*)bmg)[i];
    }
    __syncthreads();

    const uint32_t ksb = (uint32_t)__cvta_generic_to_shared(&ks[wid][0]);
    const uint32_t bmb = (uint32_t)__cvta_generic_to_shared(&bm[0]);

    const int  r0 = lane;
    const bool v1 = (lane < 17);
    const int  r1 = v1 ? lane + 32 : 48;   // clamped; results discarded when !v1

    // ---- phase 1: packed logits, 2 rows/thread; q streamed from gmem ----
    unsigned long long acc0[26], acc1[26];
    #pragma unroll
    for (int p = 0; p < 26; p++) { acc0[p] = 0ull; acc1[p] = 0ull; }

    #pragma unroll 4
    for (int c = 0; c < DK; c++) {
        const uint32_t rowb = ksb + (uint32_t)(c * LP) * 4u;
        float q0 = __ldg(qg + c * LW + r0);      // coalesced across lanes
        float q1 = __ldg(qg + c * LW + r1);      // coalesced across lanes
        unsigned long long q0p = pack2(q0, q0);
        unsigned long long q1p = pack2(q1, q1);
        #pragma unroll
        for (int j = 0; j < 13; j++) {
            unsigned long long k0, k1;
            lds_v2u64(rowb + j * 16, k0, k1);
            acc0[2 * j]     = fma2(q0p, k0, acc0[2 * j]);
            acc0[2 * j + 1] = fma2(q0p, k1, acc0[2 * j + 1]);
            acc1[2 * j]     = fma2(q1p, k0, acc1[2 * j]);
            acc1[2 * j + 1] = fma2(q1p, k1, acc1[2 * j + 1]);
        }
    }

    // ---- softmax (packed where possible) ----
    const float scale = 0.17677669529663687f;  // 32^-0.5
    const unsigned long long scale2 = pack2(scale, scale);
    const uint32_t bmr0 = bmb + (uint32_t)(r0 * RST) * 4u;
    const uint32_t bmr1 = bmb + (uint32_t)(r1 * RST) * 4u;

    #define SOFTMAX_ROW(ACC, BMR)                                            \
    {                                                                        \
        float mx = -1e30f, u, v;                                             \
        _Pragma("unroll")                                                    \
        for (int p = 0; p < 24; p++) {                                       \
            ACC[p] = fma2(ACC[p], scale2, lds_u64(BMR + p * 8));             \
            unpack2(ACC[p], u, v);                                           \
            mx = fmaxf(mx, fmaxf(u, v));                                     \
        }                                                                    \
        unpack2(ACC[24], u, v);                                              \
        float x48 = fmaf(u, scale, lds_f32(BMR + 48 * 4));                   \
        mx = fmaxf(mx, x48);                                                 \
        float sum = 0.f;                                                     \
        _Pragma("unroll")                                                    \
        for (int p = 0; p < 24; p++) {                                       \
            unpack2(ACC[p], u, v);                                           \
            u = __expf(u - mx); v = __expf(v - mx);                          \
            sum += u + v;                                                    \
            ACC[p] = pack2(u, v);                                            \
        }                                                                    \
        float e48 = __expf(x48 - mx);                                        \
        sum += e48;                                                          \
        ACC[24] = pack2(e48, 0.f);                                           \
        float inv = 1.0f / sum;                                              \
        unsigned long long inv2 = pack2(inv, inv);                           \
        _Pragma("unroll")                                                    \
        for (int p = 0; p < 25; p++) ACC[p] = mul2(ACC[p], inv2);            \
        ACC[25] = 0ull;                                                      \
    }

    SOFTMAX_ROW(acc0, bmr0)
    SOFTMAX_ROW(acc1, bmr1)

    // ---- phase 2: score[c][t] = sum_s p[s] * k[c][s] (V := K) ----
    float* __restrict__ og = out_score + (size_t)bh * (DK * LW);
    #pragma unroll 2
    for (int c = 0; c < DK; c++) {
        const uint32_t rowb = ksb + (uint32_t)(c * LP) * 4u;
        unsigned long long s0 = 0ull, s1 = 0ull;
        #pragma unroll
        for (int j = 0; j < 13; j++) {
            unsigned long long k0, k1;
            lds_v2u64(rowb + j * 16, k0, k1);
            s0 = fma2(acc0[2 * j], k0, s0);
            s0 = fma2(acc0[2 * j + 1], k1, s0);
            s1 = fma2(acc1[2 * j], k0, s1);
            s1 = fma2(acc1[2 * j + 1], k1, s1);
        }
        float a, bb, x, y;
        unpack2(s0, a, bb);
        unpack2(s1, x, y);
        og[c * LW + r0] = a + bb;
        if (v1) og[c * LW + r1] = x + y;
    }
    __syncwarp();

    // ---- attn write-out, staging through ks[wid] (dead after phase 2) ----
    float* __restrict__ ag = out_attn + (size_t)bh * (LW * LW);

    // chunk A: rows 0..31 (each lane's r0 row), 32*50 = 1600 <= 1664 floats
    #pragma unroll
    for (int p = 0; p < 25; p++) sts_u64(ksb + (uint32_t)(lane * RST) * 4u + p * 8, acc0[p]);
    __syncwarp();
    for (int i = lane; i < 32 * LW; i += 32) {
        int t = i / LW, s = i - t * LW;
        ag[i] = ks[wid][t * RST + s];
    }
    __syncwarp();

    // chunk B: rows 32..48 (lanes 0..16 hold them), 17*50 = 850 floats
    if (v1) {
        #pragma unroll
        for (int p = 0; p < 25; p++) sts_u64(ksb + (uint32_t)(lane * RST) * 4u + p * 8, acc1[p]);
    }
    __syncwarp();
    for (int i = lane; i < 17 * LW; i += 32) {
        int t = i / LW, s = i - t * LW;
        ag[32 * LW + i] = ks[wid][t * RST + s];
    }
}

extern "C" void kernel_launch(void* const* d_in, const int* in_sizes, int n_in,
                              void* d_out, int out_size) {
    const float* q     = (const float*)d_in[0];
    const float* k     = (const float*)d_in[1];
    // d_in[2] (v) unused: reference sets v := k
    const float* mask  = (const float*)d_in[3];
    const float* table = (const float*)d_in[4];
    const int*   idx   = (const int*)d_in[5];

    float* out       = (float*)d_out;
    float* out_score = out;                            // 2048*256*49
    float* out_attn  = out + (size_t)2048 * 256 * 49;  // 2048*8*49*49

    bm_prep_kernel<<<NH * NW, 256>>>(table, idx, mask);
    win_attn_kernel<<<NW * NH * 8, 128>>>(q, k, out_score, out_attn);
}